// round 14
// baseline (speedup 1.0000x reference)
#include <cuda_runtime.h>
#include <cuda_fp16.h>
#include <cstdint>
#include <cstddef>

#define TBROWS 2048
#define VOC    50000
#define KDIM   512
#define SLEN   50
#define BATCH  32
#define EPSV   1e-10f
#define BM     128
#define BN2    256        // CTA n-tile (two 128-subtiles)
#define NKCH   8          // K chunks of 64 fp16 (128 B rows)
#define NTN    391        // 128-col subtiles (storage granularity)
#define NTN2   196        // ceil(50000/256) CTA n-tiles
#define NTILE2 (16 * NTN2) // 3136 CTA tiles
#define NTILES (16 * NTN)  // 6256 storage subtiles
#define NCTA   296        // 2 CTAs/SM x 148 SMs
#define LOG_EPS (-23.025850929940457f)

// ---------------- device scratch (static; no runtime allocation) ----------------
__device__ __align__(1024) __half g_Wh[(size_t)VOC * KDIM];            // 51.2 MB
__device__ __align__(1024) __half g_hh[(size_t)TBROWS * KDIM];         // 2 MB (L2-resident)
__device__ __align__(1024) uint32_t g_logit32[(size_t)NTILES * 8192];  // 205 MB fp16 logits, tiled+swizzled
__device__ float  g_Zp[(size_t)TBROWS * NTN];  // per (row, 128-subtile) partial Z
__device__ float  g_e0v[TBROWS];               // exp(logit[:,PAD])
__device__ float  g_copyv[TBROWS];             // sigmoid(logit[:,COPY])
__device__ int    g_fixc[TBROWS * SLEN];       // scatter cols (-1 = skip)
__device__ float  g_fixv[TBROWS * SLEN];       // scatter additive term (already /norm)
__device__ float4 g_rowp[TBROWS];              // {s1, padv, log(s1), unused}

// ---------------- PTX helpers (plain sm_103 target only) ----------------
__device__ __forceinline__ uint32_t smem_u32(const void* p) {
    uint32_t a;
    asm("{ .reg .u64 t; cvta.to.shared.u64 t, %1; cvt.u32.u64 %0, t; }" : "=r"(a) : "l"(p));
    return a;
}
#define SWZ(x) ((x) ^ (((x) >> 3) & 0x70))

__device__ __forceinline__ void cp16(uint32_t dst, const void* src) {
    asm volatile("cp.async.cg.shared.global [%0], [%1], 16;" :: "r"(dst), "l"(src));
}
__device__ __forceinline__ void cp16z(uint32_t dst, const void* src, int okbytes) {
    asm volatile("cp.async.cg.shared.global [%0], [%1], 16, %2;"
                 :: "r"(dst), "l"(src), "r"(okbytes));
}
__device__ __forceinline__ void cp_commit() { asm volatile("cp.async.commit_group;"); }
__device__ __forceinline__ void cp_wait0()  { asm volatile("cp.async.wait_group 0;"); }

__device__ __forceinline__ void ldsm4(uint32_t* r, uint32_t addr) {
    asm volatile("ldmatrix.sync.aligned.m8n8.x4.shared.b16 {%0,%1,%2,%3}, [%4];"
                 : "=r"(r[0]), "=r"(r[1]), "=r"(r[2]), "=r"(r[3]) : "r"(addr));
}
// fp16-accumulate HMMA
__device__ __forceinline__ void mma16816h(uint32_t* d, const uint32_t* a,
                                          uint32_t b0, uint32_t b1) {
    asm volatile(
        "mma.sync.aligned.m16n8k16.row.col.f16.f16.f16.f16 "
        "{%0,%1}, {%2,%3,%4,%5}, {%6,%7}, {%0,%1};"
        : "+r"(d[0]), "+r"(d[1])
        : "r"(a[0]), "r"(a[1]), "r"(a[2]), "r"(a[3]), "r"(b0), "r"(b1));
}

__device__ __forceinline__ void stcs4(float* p, float4 v) {
    asm volatile("st.global.cs.v4.f32 [%0], {%1,%2,%3,%4};"
                 :: "l"(p), "f"(v.x), "f"(v.y), "f"(v.z), "f"(v.w) : "memory");
}

// FMA/ALU-pipe exp (deg-4 2^f, rel err < 5e-5) — runs parallel to MUFU.
__device__ __forceinline__ float pexp(float x) {
    float y = x * 1.4426950408889634f;
    float r = __fadd_rn(y, 12582912.0f);
    int   i = __float_as_int(r) - 0x4B400000;
    float f = __fsub_rn(y, __fsub_rn(r, 12582912.0f));
    float p = fmaf(f, 0.00961813f, 0.05550411f);
    p = fmaf(f, p, 0.24022651f);
    p = fmaf(f, p, 0.69314718f);
    p = fmaf(f, p, 1.0f);
    return __int_as_float(__float_as_int(p) + (i << 23));
}

// Tile fragment-layout index (u32 units, 8192 per 128x128 subtile) + XOR swizzle.
__device__ __forceinline__ int sw_of_idx(int idx) {
    return idx ^ (((idx >> 5) & 7) << 2) ^ (((idx >> 10) & 1) << 1) ^ ((idx >> 9) & 1);
}
__device__ __forceinline__ int sw_idx(int rr, int cu) {
    int idx = (((rr >> 5) * 2 + (cu >> 5)) << 10) | (((cu >> 2) & 7) << 7)
            | ((rr & 7) << 4) | ((cu & 3) << 2) | (((rr >> 4) & 1) << 1) | ((rr >> 3) & 1);
    return sw_of_idx(idx);
}

__device__ __forceinline__ uint32_t packhf(float a, float b) {
    __half2 t = __floats2half2_rn(a, b);
    return *(uint32_t*)&t;
}

// ---------------- kernel 1: fp32 -> fp16 conversion (32 B per thread) ----------------
__global__ void __launch_bounds__(256) prep_kernel(const float4* __restrict__ W4,
                                                   const float4* __restrict__ h4) {
    int i = blockIdx.x * 256 + threadIdx.x;     // 32-byte units
    const int WN2 = VOC * KDIM / 8;
    if (i < WN2) {
        float4 v0 = W4[2 * i], v1 = W4[2 * i + 1];
        ((uint4*)g_Wh)[i] = make_uint4(packhf(v0.x, v0.y), packhf(v0.z, v0.w),
                                       packhf(v1.x, v1.y), packhf(v1.z, v1.w));
    }
    const int HN2 = TBROWS * KDIM / 8;
    if (i < HN2) {
        float4 v0 = h4[2 * i], v1 = h4[2 * i + 1];
        ((uint4*)g_hh)[i] = make_uint4(packhf(v0.x, v0.y), packhf(v0.z, v0.w),
                                       packhf(v1.x, v1.y), packhf(v1.z, v1.w));
    }
}

// ---------------- kernel 2: fp16 HMMA GEMM, 128x256 tile, 2-stage / 1-barrier ----------------
__device__ __forceinline__ void loadChunk(int tid, int m0, int n0, int kk,
                                          uint32_t aDst, uint32_t bDst) {
#pragma unroll
    for (int i = 0; i < 4; i++) {                 // A: 1024 16B segs (128 rows x 8)
        int flat = i * 256 + tid;
        int r = flat >> 3, s = flat & 7;
        uint32_t off = SWZ((uint32_t)(r * 128 + s * 16));
        cp16(aDst + off, g_hh + (size_t)(m0 + r) * KDIM + kk * 64 + s * 8);
    }
#pragma unroll
    for (int i = 0; i < 8; i++) {                 // B: 2048 16B segs (256 rows x 8)
        int flat = i * 256 + tid;
        int r = flat >> 3, s = flat & 7;
        uint32_t off = SWZ((uint32_t)(r * 128 + s * 16));
        int gr = n0 + r;
        int ok = (gr < VOC) ? 16 : 0;
        cp16z(bDst + off,
              g_Wh + (size_t)((gr < VOC) ? gr : (VOC - 1)) * KDIM + kk * 64 + s * 8, ok);
    }
    cp_commit();
}

__global__ void __launch_bounds__(256, 2) gemm_kernel(const float* __restrict__ bias) {
    extern __shared__ char dsm[];
    __shared__ float s_bias[256];

    const int tid  = threadIdx.x;
    const int lane = tid & 31;
    const int wid  = tid >> 5;
    const int wm   = wid >> 1;       // 0..3 (m quarter)
    const int wn   = wid & 1;        // 0..1 (128-col subtile)
    const int lq   = lane >> 2;
    const int lr   = lane & 3;

    uint32_t sraw  = smem_u32(dsm);
    uint32_t aBase = (sraw + 1023u) & ~1023u;
    uint32_t aS[2] = { aBase,          aBase + 49152u };
    uint32_t bS[2] = { aBase + 16384u, aBase + 65536u };

    // ---- fragment address decomposition: base + ((ks*32) ^ xk) ----
    uint32_t aRow[2], aXk;
    uint32_t bRow[8], bXk[8];
    {
        int rl = lane & 15;
        int kh16 = ((lane >> 4) & 1) << 4;
#pragma unroll
        for (int mi = 0; mi < 2; mi++) {
            int rowA = wm * 32 + mi * 16 + rl;
            aRow[mi] = (uint32_t)(rowA * 128);
        }
        aXk = (uint32_t)(kh16 ^ (((wm * 32 + rl) & 7) << 4));
#pragma unroll
        for (int nf2 = 0; nf2 < 8; nf2++) {
            int rowB = wn * 128 + nf2 * 16 + rl;
            bRow[nf2] = (uint32_t)(rowB * 128);
            bXk[nf2]  = (uint32_t)(kh16 ^ ((rowB & 7) << 4));
        }
    }

    int tile = blockIdx.x;
    if (tile < NTILE2)
        loadChunk(tid, (tile & 15) * BM, (tile >> 4) * BN2, 0, aS[0], bS[0]);

    for (; tile < NTILE2; tile += NCTA) {
        const int m0 = (tile & 15) * BM;
        const int j  = tile >> 4;
        const int n0 = j * BN2;
        s_bias[tid] = (n0 + tid < VOC) ? bias[n0 + tid] : 0.0f;

        uint32_t acc[2][16][2];      // fp16x2 accumulators
#pragma unroll
        for (int mi = 0; mi < 2; mi++)
#pragma unroll
            for (int nf = 0; nf < 16; nf++) {
                acc[mi][nf][0] = 0u;
                acc[mi][nf][1] = 0u;
            }

#pragma unroll
        for (int kk = 0; kk < NKCH; kk++) {
            cp_wait0();
            __syncthreads();
            if (kk + 1 < NKCH) {
                loadChunk(tid, m0, n0, kk + 1, aS[(kk + 1) & 1], bS[(kk + 1) & 1]);
            } else {
                int nt = tile + NCTA;
                if (nt < NTILE2)
                    loadChunk(tid, (nt & 15) * BM, (nt >> 4) * BN2, 0, aS[0], bS[0]);
            }

            uint32_t ab = aS[kk & 1];
            uint32_t bb = bS[kk & 1];
#pragma unroll
            for (int ks = 0; ks < 4; ks++) {
                const uint32_t ko = (uint32_t)(ks * 32);
                uint32_t a[2][4];
                ldsm4(a[0], ab + aRow[0] + (ko ^ aXk));
                ldsm4(a[1], ab + aRow[1] + (ko ^ aXk));
#pragma unroll
                for (int nf2 = 0; nf2 < 8; nf2++) {
                    uint32_t b[4];
                    ldsm4(b, bb + bRow[nf2] + (ko ^ bXk[nf2]));
                    mma16816h(acc[0][nf2 * 2],     a[0], b[0], b[2]);
                    mma16816h(acc[0][nf2 * 2 + 1], a[0], b[1], b[3]);
                    mma16816h(acc[1][nf2 * 2],     a[1], b[0], b[2]);
                    mma16816h(acc[1][nf2 * 2 + 1], a[1], b[1], b[3]);
                }
            }
        }

        // ---- epilogue: per-warp 128-col subtile js = 2j + wn ----
        const int js = j * 2 + wn;
        if (js < NTN) {
            const int n0s  = n0 + wn * 128;
            const int vrem = VOC - n0s;
            const size_t tb = (size_t)(js * 16 + (tile & 15)) * 8192;
            float zs[2][2] = {{0.0f, 0.0f}, {0.0f, 0.0f}};
#pragma unroll
            for (int nf = 0; nf < 16; nf++) {
                const int cl = nf * 8 + lr * 2;
                const float bi0 = s_bias[wn * 128 + cl];
                const float bi1 = s_bias[wn * 128 + cl + 1];
                uint32_t vals[4];
#pragma unroll
                for (int mi = 0; mi < 2; mi++) {
                    float2 fA = __half22float2(*(__half2*)&acc[mi][nf][0]);
                    float2 fB = __half22float2(*(__half2*)&acc[mi][nf][1]);
                    float lA0 = fA.x + bi0, lA1 = fA.y + bi1;
                    float lB0 = fB.x + bi0, lB1 = fB.y + bi1;
                    float eA0 = __expf(lA0), eA1 = pexp(lA1);
                    float eB0 = __expf(lB0), eB1 = pexp(lB1);
                    if (n0s == 0 && nf == 0) {
                        const int rA = m0 + wm * 32 + mi * 16 + lq;
                        if (lr == 0) { g_e0v[rA] = eA0; g_e0v[rA + 8] = eB0; }
                        if (lr == 2) {
                            g_copyv[rA]     = 1.0f / (1.0f + __expf(-lA0));
                            g_copyv[rA + 8] = 1.0f / (1.0f + __expf(-lB0));
                            eA0 = 0.0f; eB0 = 0.0f;       // COPY masked from softmax
                        }
                    }
                    if (cl     >= vrem) { eA0 = 0.0f; eB0 = 0.0f; }
                    if (cl + 1 >= vrem) { eA1 = 0.0f; eB1 = 0.0f; }
                    zs[mi][0] += eA0 + eA1;
                    zs[mi][1] += eB0 + eB1;
                    vals[mi * 2 + 0] = packhf(lA0, lA1);
                    vals[mi * 2 + 1] = packhf(lB0, lB1);
                }
                const int idx0 = (wm * 2 + (nf >> 3)) * 1024 + (nf & 7) * 128
                               + lq * 16 + lr * 4;
                const int s0 = sw_of_idx(idx0);
                uint32_t arr[4];
                const int c0 = s0 & 3;
                arr[c0 ^ 0] = vals[0];
                arr[c0 ^ 1] = vals[1];
                arr[c0 ^ 2] = vals[2];
                arr[c0 ^ 3] = vals[3];
                *(uint4*)(g_logit32 + tb + (s0 & ~3)) =
                    make_uint4(arr[0], arr[1], arr[2], arr[3]);
            }
#pragma unroll
            for (int mi = 0; mi < 2; mi++)
#pragma unroll
                for (int h = 0; h < 2; h++) {
                    float s = zs[mi][h];
                    s += __shfl_xor_sync(0xFFFFFFFFu, s, 1);
                    s += __shfl_xor_sync(0xFFFFFFFFu, s, 2);
                    if (lr == 0) {
                        const int grow = m0 + wm * 32 + mi * 16 + h * 8 + lq;
                        g_Zp[(size_t)grow * NTN + js] = s;
                    }
                }
        }
        __syncthreads();   // protect s_bias rewrite at next tile top
    }
}

// ---------------- kernel 3: per-row params (Z, norm, scatter dedup) ----------------
__global__ void __launch_bounds__(64) rowparams_kernel(const float* __restrict__ attn,
                                                       const int* __restrict__ src,
                                                       const int* __restrict__ alignment) {
    __shared__ float s_red[64];
    __shared__ float s_attn[SLEN];
    __shared__ int   s_idx[SLEN];
    __shared__ float s_c, s_norm;

    const int r = blockIdx.x, t = threadIdx.x;
    float z = 0.0f;
    for (int j = t; j < NTN; j += 64) z += g_Zp[(size_t)r * NTN + j];
    s_red[t] = z;
    __syncthreads();
    for (int o = 32; o > 0; o >>= 1) {
        if (t < o) s_red[t] += s_red[t + o];
        __syncthreads();
    }
    if (t < SLEN) {
        s_attn[t] = attn[r * SLEN + t];
        int bb = r % BATCH;
        s_idx[t] = alignment[src[bb * SLEN + t]];
    }
    __syncthreads();
    if (t == 0) {
        float Z  = s_red[0];
        float c  = g_copyv[r];
        float e0 = g_e0v[r];
        float sa = 0.0f, A0 = 0.0f;
        for (int s = 0; s < SLEN; s++) {
            sa += s_attn[s];
            if (s_idx[s] == 0) A0 += s_attn[s];
        }
        float norm = EPSV + (1.0f - c) * (1.0f - e0 / Z) + c * (sa - A0);
        s_c = c; s_norm = norm;
        float s1 = (1.0f - c) / (Z * norm);
        float padv = logf(EPSV / norm + EPSV);
        g_rowp[r] = make_float4(s1, padv, logf(s1), 0.0f);
    }
    __syncthreads();
    if (t < SLEN) {
        int idx = s_idx[t];
        int owner = (idx != 0);
        float sum = 0.0f;
        for (int s = 0; s < SLEN; s++) {
            if (s_idx[s] == idx) {
                if (s < t) owner = 0;
                sum += s_attn[s];
            }
        }
        if (owner) {
            g_fixc[r * SLEN + t] = idx;
            g_fixv[r * SLEN + t] = s_c * sum / s_norm;
        } else {
            g_fixc[r * SLEN + t] = -1;
        }
    }
}

// ---------------- kernel 4: tile un-permute, warp-per-row coalesced streaming stores ----------------
__global__ void __launch_bounds__(512) final_kernel(float* __restrict__ out) {
    __shared__ uint32_t s_t[8192];       // 32 KB subtile
    __shared__ float s_C[128];

    const int tile = blockIdx.x;
    const int m0 = (tile & 15) * BM;
    const int j  = tile >> 4;
    const int n0 = j * 128;
    const int tid = threadIdx.x;
    const int lane = tid & 31;
    const int warp = tid >> 5;           // 0..15

    const uint32_t sbase = smem_u32(s_t);
    const uint4* gt = (const uint4*)(g_logit32 + (size_t)tile * 8192);
#pragma unroll
    for (int i = 0; i < 4; i++) {
        int f = i * 512 + tid;
        cp16(sbase + (uint32_t)f * 16u, gt + f);
    }
    cp_commit();
    if (tid < 128) s_C[tid] = g_rowp[m0 + tid].z;
    cp_wait0();
    __syncthreads();

    // incremental swizzle: sa(r8) = sa_base ^ (r8<<4) ^ (((r8>>1)&3)<<2)
    const int sa_base = sw_idx(warp * 8, lane * 2);
    const bool full = (n0 + 128 <= VOC); // false only on the last subtile (vrem=80)
    float* orow = out + (size_t)(m0 + warp * 8) * VOC + n0 + lane * 4;
#pragma unroll
    for (int r8 = 0; r8 < 8; r8++) {
        const int row = warp * 8 + r8;
        const float C = s_C[row];
        const int sa = sa_base ^ (r8 << 4) ^ (((r8 >> 1) & 3) << 2);
        uint32_t a = s_t[sa];
        uint32_t b = s_t[sa ^ 4];
        __half2 ha = *(__half2*)&a, hb = *(__half2*)&b;
        float2 fa = __half22float2(ha), fb = __half22float2(hb);
        float4 v = make_float4(fa.x + C, fa.y + C, fb.x + C, fb.y + C);
        if (j == 0) {
            if (lane == 0) v.x = g_rowp[m0 + row].y;   // PAD
            if (lane == 1) v.x = LOG_EPS;              // COPY default (fixup may overwrite)
        }
        if (full || lane < 20)
            stcs4(orow, v);
        orow += VOC;
    }
}

// ---------------- kernel 5: scatter fix-ups ----------------
__global__ void __launch_bounds__(64) fixup_kernel(float* __restrict__ out) {
    const int r = blockIdx.x, t = threadIdx.x;
    if (t >= SLEN) return;
    int cidx = g_fixc[r * SLEN + t];
    if (cidx < 0) return;
    int mt = r >> 7, rr = r & 127;
    int j = cidx >> 7, cc = cidx & 127;
    size_t gi = (size_t)(j * 16 + mt) * 8192 + sw_idx(rr, cc >> 1);
    uint32_t a = g_logit32[gi];
    __half2 h = *(__half2*)&a;
    float l = (cidx & 1) ? __half2float(h.y) : __half2float(h.x);
    float e = (cidx == 4) ? 0.0f : __expf(l);
    float v = fmaf(e, g_rowp[r].x, g_fixv[r * SLEN + t] + EPSV);
    out[(size_t)r * VOC + cidx] = logf(v);
}

// ---------------- launch ----------------
extern "C" void kernel_launch(void* const* d_in, const int* in_sizes, int n_in,
                              void* d_out, int out_size) {
    const float* hidden    = (const float*)d_in[0];
    const float* attn      = (const float*)d_in[1];
    const float* W         = (const float*)d_in[2];
    const float* b         = (const float*)d_in[3];
    const int*   src       = (const int*)d_in[4];
    const int*   alignment = (const int*)d_in[5];
    float* out = (float*)d_out;

    // pad(1K) + 2 stages x 48 KB = 97 KB -> 2 CTAs/SM (194 KB < 228 KB)
    const int dyn_smem = 1024 + 2 * 49152;
    cudaFuncSetAttribute(gemm_kernel, cudaFuncAttributeMaxDynamicSharedMemorySize, dyn_smem);

    prep_kernel<<<12500, 256>>>((const float4*)W, (const float4*)hidden);
    gemm_kernel<<<NCTA, 256, dyn_smem>>>(b);
    rowparams_kernel<<<TBROWS, 64>>>(attn, src, alignment);
    final_kernel<<<NTILES, 512>>>(out);
    fixup_kernel<<<TBROWS, 64>>>(out);
}

// round 15
// speedup vs baseline: 1.0050x; 1.0050x over previous
#include <cuda_runtime.h>
#include <cuda_fp16.h>
#include <cstdint>
#include <cstddef>

#define TBROWS 2048
#define VOC    50000
#define KDIM   512
#define SLEN   50
#define BATCH  32
#define EPSV   1e-10f
#define BM     128
#define BN2    256        // CTA n-tile (two 128-subtiles)
#define NKCH   8          // K chunks of 64 fp16 (128 B rows)
#define NTN    391        // 128-col subtiles (storage granularity)
#define NTN2   196        // ceil(50000/256) CTA n-tiles
#define NTILE2 (16 * NTN2) // 3136 CTA tiles
#define NTILES (16 * NTN)  // 6256 storage subtiles
#define NCTA   296        // 2 CTAs/SM x 148 SMs
#define LOG_EPS (-23.025850929940457f)

// ---------------- device scratch (static; no runtime allocation) ----------------
__device__ __align__(1024) __half g_Wh[(size_t)VOC * KDIM];            // 51.2 MB
__device__ __align__(1024) __half g_hh[(size_t)TBROWS * KDIM];         // 2 MB (L2-resident)
__device__ __align__(1024) uint32_t g_logit32[(size_t)NTILES * 8192];  // 205 MB fp16 logits, tiled+swizzled
__device__ float  g_Zp[(size_t)TBROWS * NTN];  // per (row, 128-subtile) partial Z
__device__ float  g_e0v[TBROWS];               // exp(logit[:,PAD])
__device__ float  g_copyv[TBROWS];             // sigmoid(logit[:,COPY])
__device__ int    g_fixc[TBROWS * SLEN];       // scatter cols (-1 = skip)
__device__ float  g_fixv[TBROWS * SLEN];       // scatter additive term (already /norm)
__device__ float4 g_rowp[TBROWS];              // {s1, padv, log(s1), unused}

// ---------------- PTX helpers (plain sm_103 target only) ----------------
__device__ __forceinline__ uint32_t smem_u32(const void* p) {
    uint32_t a;
    asm("{ .reg .u64 t; cvta.to.shared.u64 t, %1; cvt.u32.u64 %0, t; }" : "=r"(a) : "l"(p));
    return a;
}
#define SWZ(x) ((x) ^ (((x) >> 3) & 0x70))

__device__ __forceinline__ void cp16(uint32_t dst, const void* src) {
    asm volatile("cp.async.cg.shared.global [%0], [%1], 16;" :: "r"(dst), "l"(src));
}
__device__ __forceinline__ void cp16z(uint32_t dst, const void* src, int okbytes) {
    asm volatile("cp.async.cg.shared.global [%0], [%1], 16, %2;"
                 :: "r"(dst), "l"(src), "r"(okbytes));
}
__device__ __forceinline__ void cp_commit() { asm volatile("cp.async.commit_group;"); }
__device__ __forceinline__ void cp_wait0()  { asm volatile("cp.async.wait_group 0;"); }

__device__ __forceinline__ void ldsm4(uint32_t* r, uint32_t addr) {
    asm volatile("ldmatrix.sync.aligned.m8n8.x4.shared.b16 {%0,%1,%2,%3}, [%4];"
                 : "=r"(r[0]), "=r"(r[1]), "=r"(r[2]), "=r"(r[3]) : "r"(addr));
}
// fp16-accumulate HMMA
__device__ __forceinline__ void mma16816h(uint32_t* d, const uint32_t* a,
                                          uint32_t b0, uint32_t b1) {
    asm volatile(
        "mma.sync.aligned.m16n8k16.row.col.f16.f16.f16.f16 "
        "{%0,%1}, {%2,%3,%4,%5}, {%6,%7}, {%0,%1};"
        : "+r"(d[0]), "+r"(d[1])
        : "r"(a[0]), "r"(a[1]), "r"(a[2]), "r"(a[3]), "r"(b0), "r"(b1));
}

// FMA/ALU-pipe exp (deg-4 2^f, rel err < 5e-5) — runs parallel to MUFU.
__device__ __forceinline__ float pexp(float x) {
    float y = x * 1.4426950408889634f;
    float r = __fadd_rn(y, 12582912.0f);
    int   i = __float_as_int(r) - 0x4B400000;
    float f = __fsub_rn(y, __fsub_rn(r, 12582912.0f));
    float p = fmaf(f, 0.00961813f, 0.05550411f);
    p = fmaf(f, p, 0.24022651f);
    p = fmaf(f, p, 0.69314718f);
    p = fmaf(f, p, 1.0f);
    return __int_as_float(__float_as_int(p) + (i << 23));
}

// Tile fragment-layout index (u32 units, 8192 per 128x128 subtile) + XOR swizzle.
__device__ __forceinline__ int sw_of_idx(int idx) {
    return idx ^ (((idx >> 5) & 7) << 2) ^ (((idx >> 10) & 1) << 1) ^ ((idx >> 9) & 1);
}
__device__ __forceinline__ int sw_idx(int rr, int cu) {
    int idx = (((rr >> 5) * 2 + (cu >> 5)) << 10) | (((cu >> 2) & 7) << 7)
            | ((rr & 7) << 4) | ((cu & 3) << 2) | (((rr >> 4) & 1) << 1) | ((rr >> 3) & 1);
    return sw_of_idx(idx);
}

__device__ __forceinline__ uint32_t packhf(float a, float b) {
    __half2 t = __floats2half2_rn(a, b);
    return *(uint32_t*)&t;
}

// ---------------- kernel 1: fp32 -> fp16 conversion (32 B per thread) ----------------
__global__ void __launch_bounds__(256) prep_kernel(const float4* __restrict__ W4,
                                                   const float4* __restrict__ h4) {
    int i = blockIdx.x * 256 + threadIdx.x;     // 32-byte units
    const int WN2 = VOC * KDIM / 8;
    if (i < WN2) {
        float4 v0 = W4[2 * i], v1 = W4[2 * i + 1];
        ((uint4*)g_Wh)[i] = make_uint4(packhf(v0.x, v0.y), packhf(v0.z, v0.w),
                                       packhf(v1.x, v1.y), packhf(v1.z, v1.w));
    }
    const int HN2 = TBROWS * KDIM / 8;
    if (i < HN2) {
        float4 v0 = h4[2 * i], v1 = h4[2 * i + 1];
        ((uint4*)g_hh)[i] = make_uint4(packhf(v0.x, v0.y), packhf(v0.z, v0.w),
                                       packhf(v1.x, v1.y), packhf(v1.z, v1.w));
    }
}

// ---------------- kernel 2: fp16 HMMA GEMM, 128x256 tile, 2-stage / 1-barrier ----------------
__device__ __forceinline__ void loadChunk(int tid, int m0, int n0, int kk,
                                          uint32_t aDst, uint32_t bDst) {
#pragma unroll
    for (int i = 0; i < 4; i++) {                 // A: 1024 16B segs (128 rows x 8)
        int flat = i * 256 + tid;
        int r = flat >> 3, s = flat & 7;
        uint32_t off = SWZ((uint32_t)(r * 128 + s * 16));
        cp16(aDst + off, g_hh + (size_t)(m0 + r) * KDIM + kk * 64 + s * 8);
    }
#pragma unroll
    for (int i = 0; i < 8; i++) {                 // B: 2048 16B segs (256 rows x 8)
        int flat = i * 256 + tid;
        int r = flat >> 3, s = flat & 7;
        uint32_t off = SWZ((uint32_t)(r * 128 + s * 16));
        int gr = n0 + r;
        int ok = (gr < VOC) ? 16 : 0;
        cp16z(bDst + off,
              g_Wh + (size_t)((gr < VOC) ? gr : (VOC - 1)) * KDIM + kk * 64 + s * 8, ok);
    }
    cp_commit();
}

__global__ void __launch_bounds__(256, 2) gemm_kernel(const float* __restrict__ bias) {
    extern __shared__ char dsm[];
    __shared__ float s_bias[256];

    const int tid  = threadIdx.x;
    const int lane = tid & 31;
    const int wid  = tid >> 5;
    const int wm   = wid >> 1;       // 0..3 (m quarter)
    const int wn   = wid & 1;        // 0..1 (128-col subtile)
    const int lq   = lane >> 2;
    const int lr   = lane & 3;

    uint32_t sraw  = smem_u32(dsm);
    uint32_t aBase = (sraw + 1023u) & ~1023u;
    uint32_t aS[2] = { aBase,          aBase + 49152u };
    uint32_t bS[2] = { aBase + 16384u, aBase + 65536u };

    // ---- fragment address decomposition: base + ((ks*32) ^ xk) ----
    uint32_t aRow[2], aXk;
    uint32_t bRow[8], bXk[8];
    {
        int rl = lane & 15;
        int kh16 = ((lane >> 4) & 1) << 4;
#pragma unroll
        for (int mi = 0; mi < 2; mi++) {
            int rowA = wm * 32 + mi * 16 + rl;
            aRow[mi] = (uint32_t)(rowA * 128);
        }
        aXk = (uint32_t)(kh16 ^ (((wm * 32 + rl) & 7) << 4));
#pragma unroll
        for (int nf2 = 0; nf2 < 8; nf2++) {
            int rowB = wn * 128 + nf2 * 16 + rl;
            bRow[nf2] = (uint32_t)(rowB * 128);
            bXk[nf2]  = (uint32_t)(kh16 ^ ((rowB & 7) << 4));
        }
    }

    int tile = blockIdx.x;
    if (tile < NTILE2)
        loadChunk(tid, (tile & 15) * BM, (tile >> 4) * BN2, 0, aS[0], bS[0]);

    for (; tile < NTILE2; tile += NCTA) {
        const int m0 = (tile & 15) * BM;
        const int j  = tile >> 4;
        const int n0 = j * BN2;
        s_bias[tid] = (n0 + tid < VOC) ? bias[n0 + tid] : 0.0f;

        uint32_t acc[2][16][2];      // fp16x2 accumulators
#pragma unroll
        for (int mi = 0; mi < 2; mi++)
#pragma unroll
            for (int nf = 0; nf < 16; nf++) {
                acc[mi][nf][0] = 0u;
                acc[mi][nf][1] = 0u;
            }

#pragma unroll
        for (int kk = 0; kk < NKCH; kk++) {
            cp_wait0();
            __syncthreads();
            if (kk + 1 < NKCH) {
                loadChunk(tid, m0, n0, kk + 1, aS[(kk + 1) & 1], bS[(kk + 1) & 1]);
            } else {
                int nt = tile + NCTA;
                if (nt < NTILE2)
                    loadChunk(tid, (nt & 15) * BM, (nt >> 4) * BN2, 0, aS[0], bS[0]);
            }

            uint32_t ab = aS[kk & 1];
            uint32_t bb = bS[kk & 1];
#pragma unroll
            for (int ks = 0; ks < 4; ks++) {
                const uint32_t ko = (uint32_t)(ks * 32);
                uint32_t a[2][4];
                ldsm4(a[0], ab + aRow[0] + (ko ^ aXk));
                ldsm4(a[1], ab + aRow[1] + (ko ^ aXk));
#pragma unroll
                for (int nf2 = 0; nf2 < 8; nf2++) {
                    uint32_t b[4];
                    ldsm4(b, bb + bRow[nf2] + (ko ^ bXk[nf2]));
                    mma16816h(acc[0][nf2 * 2],     a[0], b[0], b[2]);
                    mma16816h(acc[0][nf2 * 2 + 1], a[0], b[1], b[3]);
                    mma16816h(acc[1][nf2 * 2],     a[1], b[0], b[2]);
                    mma16816h(acc[1][nf2 * 2 + 1], a[1], b[1], b[3]);
                }
            }
        }

        // ---- epilogue: per-warp 128-col subtile js = 2j + wn ----
        const int js = j * 2 + wn;
        if (js < NTN) {
            const int n0s  = n0 + wn * 128;
            const int vrem = VOC - n0s;
            const size_t tb = (size_t)(js * 16 + (tile & 15)) * 8192;
            float zs[2][2] = {{0.0f, 0.0f}, {0.0f, 0.0f}};
#pragma unroll
            for (int nf = 0; nf < 16; nf++) {
                const int cl = nf * 8 + lr * 2;
                const float bi0 = s_bias[wn * 128 + cl];
                const float bi1 = s_bias[wn * 128 + cl + 1];
                uint32_t vals[4];
#pragma unroll
                for (int mi = 0; mi < 2; mi++) {
                    float2 fA = __half22float2(*(__half2*)&acc[mi][nf][0]);
                    float2 fB = __half22float2(*(__half2*)&acc[mi][nf][1]);
                    float lA0 = fA.x + bi0, lA1 = fA.y + bi1;
                    float lB0 = fB.x + bi0, lB1 = fB.y + bi1;
                    float eA0 = __expf(lA0), eA1 = pexp(lA1);
                    float eB0 = __expf(lB0), eB1 = pexp(lB1);
                    if (n0s == 0 && nf == 0) {
                        const int rA = m0 + wm * 32 + mi * 16 + lq;
                        if (lr == 0) { g_e0v[rA] = eA0; g_e0v[rA + 8] = eB0; }
                        if (lr == 2) {
                            g_copyv[rA]     = 1.0f / (1.0f + __expf(-lA0));
                            g_copyv[rA + 8] = 1.0f / (1.0f + __expf(-lB0));
                            eA0 = 0.0f; eB0 = 0.0f;       // COPY masked from softmax
                        }
                    }
                    if (cl     >= vrem) { eA0 = 0.0f; eB0 = 0.0f; }
                    if (cl + 1 >= vrem) { eA1 = 0.0f; eB1 = 0.0f; }
                    zs[mi][0] += eA0 + eA1;
                    zs[mi][1] += eB0 + eB1;
                    vals[mi * 2 + 0] = packhf(lA0, lA1);
                    vals[mi * 2 + 1] = packhf(lB0, lB1);
                }
                const int idx0 = (wm * 2 + (nf >> 3)) * 1024 + (nf & 7) * 128
                               + lq * 16 + lr * 4;
                const int s0 = sw_of_idx(idx0);
                uint32_t arr[4];
                const int c0 = s0 & 3;
                arr[c0 ^ 0] = vals[0];
                arr[c0 ^ 1] = vals[1];
                arr[c0 ^ 2] = vals[2];
                arr[c0 ^ 3] = vals[3];
                *(uint4*)(g_logit32 + tb + (s0 & ~3)) =
                    make_uint4(arr[0], arr[1], arr[2], arr[3]);
            }
#pragma unroll
            for (int mi = 0; mi < 2; mi++)
#pragma unroll
                for (int h = 0; h < 2; h++) {
                    float s = zs[mi][h];
                    s += __shfl_xor_sync(0xFFFFFFFFu, s, 1);
                    s += __shfl_xor_sync(0xFFFFFFFFu, s, 2);
                    if (lr == 0) {
                        const int grow = m0 + wm * 32 + mi * 16 + h * 8 + lq;
                        g_Zp[(size_t)grow * NTN + js] = s;
                    }
                }
        }
        __syncthreads();   // protect s_bias rewrite at next tile top
    }
}

// ---------------- kernel 3: per-row params (Z, norm, scatter dedup) ----------------
__global__ void __launch_bounds__(64) rowparams_kernel(const float* __restrict__ attn,
                                                       const int* __restrict__ src,
                                                       const int* __restrict__ alignment) {
    __shared__ float s_red[64];
    __shared__ float s_attn[SLEN];
    __shared__ int   s_idx[SLEN];
    __shared__ float s_c, s_norm;

    const int r = blockIdx.x, t = threadIdx.x;
    float z = 0.0f;
    for (int j = t; j < NTN; j += 64) z += g_Zp[(size_t)r * NTN + j];
    s_red[t] = z;
    __syncthreads();
    for (int o = 32; o > 0; o >>= 1) {
        if (t < o) s_red[t] += s_red[t + o];
        __syncthreads();
    }
    if (t < SLEN) {
        s_attn[t] = attn[r * SLEN + t];
        int bb = r % BATCH;
        s_idx[t] = alignment[src[bb * SLEN + t]];
    }
    __syncthreads();
    if (t == 0) {
        float Z  = s_red[0];
        float c  = g_copyv[r];
        float e0 = g_e0v[r];
        float sa = 0.0f, A0 = 0.0f;
        for (int s = 0; s < SLEN; s++) {
            sa += s_attn[s];
            if (s_idx[s] == 0) A0 += s_attn[s];
        }
        float norm = EPSV + (1.0f - c) * (1.0f - e0 / Z) + c * (sa - A0);
        s_c = c; s_norm = norm;
        float s1 = (1.0f - c) / (Z * norm);
        float padv = logf(EPSV / norm + EPSV);
        g_rowp[r] = make_float4(s1, padv, logf(s1), 0.0f);
    }
    __syncthreads();
    if (t < SLEN) {
        int idx = s_idx[t];
        int owner = (idx != 0);
        float sum = 0.0f;
        for (int s = 0; s < SLEN; s++) {
            if (s_idx[s] == idx) {
                if (s < t) owner = 0;
                sum += s_attn[s];
            }
        }
        if (owner) {
            g_fixc[r * SLEN + t] = idx;
            g_fixv[r * SLEN + t] = s_c * sum / s_norm;
        } else {
            g_fixc[r * SLEN + t] = -1;
        }
    }
}

// ---------------- kernel 4: tile un-permute, warp-per-row coalesced stores ----------------
__global__ void __launch_bounds__(512) final_kernel(float* __restrict__ out) {
    __shared__ uint32_t s_t[8192];       // 32 KB subtile
    __shared__ float s_C[128];

    const int tile = blockIdx.x;
    const int m0 = (tile & 15) * BM;
    const int j  = tile >> 4;
    const int n0 = j * 128;
    const int tid = threadIdx.x;
    const int lane = tid & 31;
    const int warp = tid >> 5;           // 0..15

    const uint32_t sbase = smem_u32(s_t);
    const uint4* gt = (const uint4*)(g_logit32 + (size_t)tile * 8192);
#pragma unroll
    for (int i = 0; i < 4; i++) {
        int f = i * 512 + tid;
        cp16(sbase + (uint32_t)f * 16u, gt + f);
    }
    cp_commit();
    if (tid < 128) s_C[tid] = g_rowp[m0 + tid].z;
    cp_wait0();
    __syncthreads();

    // incremental swizzle: sa(r8) = sa_base ^ (r8<<4) ^ (((r8>>1)&3)<<2)
    const int sa_base = sw_idx(warp * 8, lane * 2);
    const bool full = (n0 + 128 <= VOC); // false only on the last subtile (vrem=80)
    float* orow = out + (size_t)(m0 + warp * 8) * VOC + n0 + lane * 4;
#pragma unroll
    for (int r8 = 0; r8 < 8; r8++) {
        const int row = warp * 8 + r8;
        const float C = s_C[row];
        const int sa = sa_base ^ (r8 << 4) ^ (((r8 >> 1) & 3) << 2);
        uint32_t a = s_t[sa];
        uint32_t b = s_t[sa ^ 4];
        __half2 ha = *(__half2*)&a, hb = *(__half2*)&b;
        float2 fa = __half22float2(ha), fb = __half22float2(hb);
        float4 v = make_float4(fa.x + C, fa.y + C, fb.x + C, fb.y + C);
        if (j == 0) {
            if (lane == 0) v.x = g_rowp[m0 + row].y;   // PAD
            if (lane == 1) v.x = LOG_EPS;              // COPY default (fixup may overwrite)
        }
        if (full || lane < 20)
            *(float4*)orow = v;
        orow += VOC;
    }
}

// ---------------- kernel 5: scatter fix-ups ----------------
__global__ void __launch_bounds__(64) fixup_kernel(float* __restrict__ out) {
    const int r = blockIdx.x, t = threadIdx.x;
    if (t >= SLEN) return;
    int cidx = g_fixc[r * SLEN + t];
    if (cidx < 0) return;
    int mt = r >> 7, rr = r & 127;
    int j = cidx >> 7, cc = cidx & 127;
    size_t gi = (size_t)(j * 16 + mt) * 8192 + sw_idx(rr, cc >> 1);
    uint32_t a = g_logit32[gi];
    __half2 h = *(__half2*)&a;
    float l = (cidx & 1) ? __half2float(h.y) : __half2float(h.x);
    float e = (cidx == 4) ? 0.0f : __expf(l);
    float v = fmaf(e, g_rowp[r].x, g_fixv[r * SLEN + t] + EPSV);
    out[(size_t)r * VOC + cidx] = logf(v);
}

// ---------------- launch ----------------
extern "C" void kernel_launch(void* const* d_in, const int* in_sizes, int n_in,
                              void* d_out, int out_size) {
    const float* hidden    = (const float*)d_in[0];
    const float* attn      = (const float*)d_in[1];
    const float* W         = (const float*)d_in[2];
    const float* b         = (const float*)d_in[3];
    const int*   src       = (const int*)d_in[4];
    const int*   alignment = (const int*)d_in[5];
    float* out = (float*)d_out;

    // pad(1K) + 2 stages x 48 KB = 97 KB -> 2 CTAs/SM (194 KB < 228 KB)
    const int dyn_smem = 1024 + 2 * 49152;
    cudaFuncSetAttribute(gemm_kernel, cudaFuncAttributeMaxDynamicSharedMemorySize, dyn_smem);

    prep_kernel<<<12500, 256>>>((const float4*)W, (const float4*)hidden);
    gemm_kernel<<<NCTA, 256, dyn_smem>>>(b);
    rowparams_kernel<<<TBROWS, 64>>>(attn, src, alignment);
    final_kernel<<<NTILES, 512>>>(out);
    fixup_kernel<<<TBROWS, 64>>>(out);
}